// round 12
// baseline (speedup 1.0000x reference)
#include <cuda_runtime.h>
#include <math.h>

#define P 262144          // 512*512
#define NCH 16
#define NIMG 8
#define NID 32            // ids 1..32 at row id-1; id 0 excluded (never contributes)
#define STR 17            // row stride: 17 invertible mod 32 -> conflict-free scatter
#define ACCN (NID * STR)  // 544 floats per logical accumulator
#define RREP 3            // rank replicas: band = rank/3 -> bands 0,1 cover mult<=6
#define RSTR 545          // replica stride: 545 % 32 == 1 -> same-row reps on distinct banks
#define DELTA_V 0.5f
#define DELTA_D 1.5f
#define GAMMA_W 0.001f
#define FULL 0xffffffffu

// Scratch (zero-initialized at load; k_final re-zeroes after use per replay).
__device__ float g_acc[NIMG][ACCN];   // [(id-1)*17 + e], slot 16 = count
__device__ float g_vsum[NIMG];        // per-image sum of t * invc

// Pass 1: per-segment sums + counts. grid (128, 8) x 256 thr; block = 2048 px.
// R10 config (R=3, 4 blocks/SM, 64 regs -- NO spill; R11's (,6) cap spilled v[]).
// NEW: bands 0/1 are straight-line predicated blocks (no dependent ballot chain);
// rare band>=2 stragglers handled by an off-path loop.
__global__ __launch_bounds__(256, 4) void k_accum(const float* __restrict__ emb,
                                                  const int* __restrict__ mask) {
    __shared__ float wacc[8][RREP * RSTR];   // 52.3 KB
    const int tid = threadIdx.x, w = tid >> 5, lane = tid & 31;
    const int img = blockIdx.y;

    for (int i = tid; i < 8 * RREP * RSTR; i += 256) (&wacc[0][0])[i] = 0.f;
    __syncthreads();

    const float* eb = emb + (size_t)img * NCH * P;
    const int*   mb = mask + (size_t)img * P;
    const int wbase = blockIdx.x * 2048 + w * 256;
    const unsigned below = (1u << lane) - 1u;

    for (int it = 0; it < 4; ++it) {
        const int p0 = wbase + it * 64 + lane * 2;
        const int2 mid = *reinterpret_cast<const int2*>(mb + p0);
        float v[2][NCH];
#pragma unroll
        for (int e = 0; e < NCH; e++) {
            const float2 t = *reinterpret_cast<const float2*>(eb + (size_t)e * P + p0);
            v[0][e] = t.x; v[1][e] = t.y;
        }
        const int ids[2] = {mid.x, mid.y};
#pragma unroll
        for (int s = 0; s < 2; s++) {
            const int id = ids[s];
            const bool go = (id != 0);
            const int key = go ? id : (64 + lane);        // unique keys park id0 lanes
            const unsigned peers = __match_any_sync(FULL, key);
            const int rank = __popc(peers & below);
            const int band = rank / RREP;                 // 0,1 common; >=2 rare
            const int rep  = rank - band * RREP;
            const float cntf = (float)__popc(peers);      // leader adds group count
            float* a = &wacc[w][rep * RSTR + (id - 1) * STR];

            // Common path: two independent predicated scatter blocks, no ballots.
            if (go && band == 0) {
#pragma unroll
                for (int e = 0; e < NCH; e++) a[e] += v[s][e];
                if (rank == 0) a[NCH] += cntf;            // once per id-group
            }
            if (go && band == 1) {
#pragma unroll
                for (int e = 0; e < NCH; e++) a[e] += v[s][e];
            }
            // Rare stragglers (some id has multiplicity > 6): serialized loop.
            if (__any_sync(FULL, band >= 2)) {
                for (int r = 2;; r++) {
                    if (!__ballot_sync(FULL, go && band >= r)) break;
                    if (go && band == r) {
#pragma unroll
                        for (int e = 0; e < NCH; e++) a[e] += v[s][e];
                    }
                }
            }
        }
    }
    __syncthreads();

    for (int i = tid; i < ACCN; i += 256) {
        float s = 0.f;
#pragma unroll
        for (int w2 = 0; w2 < 8; w2++) {
#pragma unroll
            for (int rp = 0; rp < RREP; rp++) s += wacc[w2][rp * RSTR + i];
        }
        atomicAdd(&g_acc[img][i], s);
    }
}

// Pass 2: variance hinge as a pure reduction: sum of t * invc[id] per image.
// Block mapping reversed vs pass 1 for L2 tail reuse. (R10 config: passed, near floor.)
__global__ __launch_bounds__(256, 5) void k_var(const float* __restrict__ emb,
                                                const int* __restrict__ mask) {
    __shared__ float mut[ACCN];          // row (id-1)*17: mean[0..15], slot16 = invc
    __shared__ float wred[8];
    const int tid = threadIdx.x, w = tid >> 5, lane = tid & 31;
    const int img = (NIMG - 1) - blockIdx.y;
    const int bx  = 127 - blockIdx.x;

    for (int i = tid; i < ACCN; i += 256) {
        const int row = i / STR, e = i % STR;
        const float cc = fmaxf(g_acc[img][row * STR + NCH], 1.f);
        mut[i] = (e == NCH) ? (1.f / cc) : (g_acc[img][row * STR + e] / cc);
    }
    __syncthreads();

    const float* eb = emb + (size_t)img * NCH * P;
    const int*   mb = mask + (size_t)img * P;
    const int wbase = bx * 2048 + w * 256;
    float vsum = 0.f;

    for (int it = 0; it < 4; ++it) {
        const int p0 = wbase + it * 64 + lane * 2;
        const int2 mid = *reinterpret_cast<const int2*>(mb + p0);
        float v[2][NCH];
#pragma unroll
        for (int e = 0; e < NCH; e++) {
            const float2 t = *reinterpret_cast<const float2*>(eb + (size_t)e * P + p0);
            v[0][e] = t.x; v[1][e] = t.y;
        }
        const int ids[2] = {mid.x, mid.y};
#pragma unroll
        for (int s = 0; s < 2; s++) {
            const int id = ids[s];
            const int row = ((id == 0) ? 1 : id) - 1;
            const float* mrow = &mut[row * STR];   // distinct rows -> distinct banks
            float sq = 0.f;
#pragma unroll
            for (int e = 0; e < NCH; e++) {
                const float d = v[s][e] - mrow[e];
                sq = fmaf(d, d, sq);
            }
            const float pd = (sq > 0.f) ? sqrtf(sq) : 0.f;
            const float tt = fmaxf(pd - DELTA_V, 0.f);
            vsum += (id != 0) ? (tt * tt * mrow[NCH]) : 0.f;
        }
    }

#pragma unroll
    for (int o = 16; o > 0; o >>= 1) vsum += __shfl_xor_sync(FULL, vsum, o);
    if (lane == 0) wred[w] = vsum;
    __syncthreads();
    if (w == 0) {
        float s = (lane < 8) ? wred[lane] : 0.f;
#pragma unroll
        for (int o = 4; o > 0; o >>= 1) s += __shfl_xor_sync(FULL, s, o);
        if (lane == 0) atomicAdd(&g_vsum[img], s);
    }
}

__device__ __forceinline__ float wsum(float x) {
#pragma unroll
    for (int o = 16; o > 0; o >>= 1) x += __shfl_xor_sync(FULL, x, o);
    return x;
}

// Finalize: one block, warp = image. Pairwise via smem broadcast reads.
__global__ __launch_bounds__(256) void k_final(float* __restrict__ out) {
    __shared__ float smu[NIMG][32][NCH + 1];
    __shared__ float sv[NIMG], sd[NIMG], sr[NIMG], sva[NIMG];
    const int tid = threadIdx.x, w = tid >> 5, lane = tid & 31;

    const float* ga = g_acc[w];
    const float cnt = ga[lane * STR + NCH];     // lane <-> instance lane+1
    const bool pres = cnt > 0.f;
    const float cc = fmaxf(cnt, 1.f);
    float mu[NCH];
#pragma unroll
    for (int e = 0; e < NCH; e++) {
        mu[e] = ga[lane * STR + e] / cc;
        smu[w][lane][e] = mu[e];
    }
    const float var_s = g_vsum[w];
    __syncwarp();

    const unsigned pb = __ballot_sync(FULL, pres);
    const float n_inst = (float)__popc(pb);

    float sqm = 0.f;
#pragma unroll
    for (int e = 0; e < NCH; e++) sqm = fmaf(mu[e], mu[e], sqm);
    const float reg_l = pres ? ((sqm > 0.f) ? sqrtf(sqm) : 0.f) : 0.f;

    float dsum = 0.f, pcount = 0.f;
#pragma unroll 4
    for (int b = 1; b < 32; b++) {
        float dsq = 0.f;
#pragma unroll
        for (int e = 0; e < NCH; e++) {
            const float d = mu[e] - smu[w][b][e];
            dsq = fmaf(d, d, dsq);
        }
        if ((lane < b) && pres && ((pb >> b) & 1u)) {
            const float dd = (dsq > 0.f) ? sqrtf(dsq) : 0.f;
            const float tt = fmaxf(2.f * DELTA_D - dd, 0.f);
            dsum = fmaf(tt, tt, dsum);
            pcount += 1.f;
        }
    }

    const float reg_t = wsum(reg_l);
    const float dst_t = wsum(dsum);
    const float pcs   = wsum(pcount);

    if (lane == 0) {
        const float valid = (n_inst > 0.f) ? 1.f : 0.f;
        const float denom = fmaxf(n_inst, 1.f);
        sv[w]  = (var_s / denom) * valid;
        sr[w]  = (reg_t / denom) * valid;
        sd[w]  = (dst_t / fmaxf(pcs, 1.f)) * ((n_inst > 1.f) ? 1.f : 0.f) * valid;
        sva[w] = valid;
    }
    __syncthreads();

    if (tid == 0) {
        float vs = 0.f, v = 0.f, d = 0.f, r = 0.f;
        for (int i = 0; i < NIMG; i++) { vs += sva[i]; v += sv[i]; d += sd[i]; r += sr[i]; }
        vs = fmaxf(vs, 1.f);
        v /= vs; d /= vs; r /= vs;
        out[0] = v + d + GAMMA_W * r;
        out[1] = v;
        out[2] = d;
        out[3] = r;
    }

    // Re-zero scratch for the next graph replay (all reads happened above).
    float* a = &g_acc[0][0];
    for (int i = tid; i < NIMG * ACCN; i += 256) a[i] = 0.f;
    if (tid < NIMG) g_vsum[tid] = 0.f;
}

extern "C" void kernel_launch(void* const* d_in, const int* in_sizes, int n_in,
                              void* d_out, int out_size) {
    const float* emb = (const float*)d_in[0];
    const int* mask = (const int*)d_in[1];
    float* out = (float*)d_out;

    k_accum<<<dim3(128, NIMG), 256>>>(emb, mask);
    k_var<<<dim3(128, NIMG), 256>>>(emb, mask);
    k_final<<<1, 256>>>(out);
}

// round 13
// speedup vs baseline: 1.3031x; 1.3031x over previous
#include <cuda_runtime.h>
#include <math.h>

#define P 262144          // 512*512
#define NCH 16
#define NIMG 8
#define NID 32            // ids 1..32 at row id-1; id 0 excluded (never contributes)
#define STR 17            // row stride: 17 invertible mod 32 -> conflict-free scatter
#define ACCN (NID * STR)  // 544 floats per logical accumulator
#define RREP 3            // rank replicas (R10 frontier: no spill at 64 regs)
#define RSTR 545          // replica stride: 545 % 32 == 1 -> same-row reps on distinct banks
#define DELTA_V 0.5f
#define DELTA_D 1.5f
#define GAMMA_W 0.001f
#define FULL 0xffffffffu
#define NVARBLK 1024      // k_var grid = 128*8

// Scratch (zero-initialized at load; finalizer re-zeroes after use per replay).
__device__ float g_acc[NIMG][ACCN];   // [(id-1)*17 + e], slot 16 = count
__device__ float g_vsum[NIMG];        // per-image sum of t * invc
__device__ unsigned g_tick;           // k_var completion ticket (atomicInc self-wraps)

// Pass 1: per-segment sums + counts. grid (64, 8) x 256 thr; block = 4096 px.
// EXACT R10 scatter core (ballot-terminated rounds = minimal wavefronts).
// grid.x halved vs R10: per-block init/reduce overhead (~950 wf) amortized 2x.
__global__ __launch_bounds__(256, 4) void k_accum(const float* __restrict__ emb,
                                                  const int* __restrict__ mask) {
    __shared__ float wacc[8][RREP * RSTR];   // 52.3 KB
    const int tid = threadIdx.x, w = tid >> 5, lane = tid & 31;
    const int img = blockIdx.y;

    for (int i = tid; i < 8 * RREP * RSTR; i += 256) (&wacc[0][0])[i] = 0.f;
    __syncthreads();

    const float* eb = emb + (size_t)img * NCH * P;
    const int*   mb = mask + (size_t)img * P;
    const int wbase = blockIdx.x * 4096 + w * 512;
    const unsigned below = (1u << lane) - 1u;

    for (int it = 0; it < 8; ++it) {
        const int p0 = wbase + it * 64 + lane * 2;
        const int2 mid = *reinterpret_cast<const int2*>(mb + p0);
        float v[2][NCH];
#pragma unroll
        for (int e = 0; e < NCH; e++) {
            const float2 t = *reinterpret_cast<const float2*>(eb + (size_t)e * P + p0);
            v[0][e] = t.x; v[1][e] = t.y;
        }
        const int ids[2] = {mid.x, mid.y};
#pragma unroll
        for (int s = 0; s < 2; s++) {
            const int id = ids[s];
            const bool go = (id != 0);
            const int key = go ? id : (64 + lane);        // unique keys park id0 lanes
            const unsigned peers = __match_any_sync(FULL, key);
            const int rank = __popc(peers & below);
            const int band = rank / RREP;
            const int rep  = rank - band * RREP;
            const float cntf = (float)__popc(peers);      // leader adds group count
            float* a = &wacc[w][rep * RSTR + (id - 1) * STR];
            for (int r = 0;; r++) {
                if (!__ballot_sync(FULL, go && band >= r)) break;
                if (go && band == r) {
#pragma unroll
                    for (int e = 0; e < NCH; e++) a[e] += v[s][e];
                    if (rank == 0) a[NCH] += cntf;        // once per id-group
                }
            }
        }
    }
    __syncthreads();

    for (int i = tid; i < ACCN; i += 256) {
        float s = 0.f;
#pragma unroll
        for (int w2 = 0; w2 < 8; w2++) {
#pragma unroll
            for (int rp = 0; rp < RREP; rp++) s += wacc[w2][rp * RSTR + i];
        }
        atomicAdd(&g_acc[img][i], s);
    }
}

__device__ __forceinline__ float wsum(float x) {
#pragma unroll
    for (int o = 16; o > 0; o >>= 1) x += __shfl_xor_sync(FULL, x, o);
    return x;
}

// Pass 2: variance hinge as a pure reduction (sum of t * invc[id] per image),
// PLUS fused finalize: the last block to finish (self-resetting ticket) computes
// the loss and re-zeroes scratch -- removes the k_final launch.
__global__ __launch_bounds__(256, 5) void k_var(const float* __restrict__ emb,
                                                const int* __restrict__ mask,
                                                float* __restrict__ out) {
    __shared__ float mut[ACCN];          // row (id-1)*17: mean[0..15], slot16 = invc
    __shared__ float wred[8];
    __shared__ int s_last;
    const int tid = threadIdx.x, w = tid >> 5, lane = tid & 31;
    const int img = (NIMG - 1) - blockIdx.y;
    const int bx  = 127 - blockIdx.x;

    for (int i = tid; i < ACCN; i += 256) {
        const int row = i / STR, e = i % STR;
        const float cc = fmaxf(g_acc[img][row * STR + NCH], 1.f);
        mut[i] = (e == NCH) ? (1.f / cc) : (g_acc[img][row * STR + e] / cc);
    }
    __syncthreads();

    const float* eb = emb + (size_t)img * NCH * P;
    const int*   mb = mask + (size_t)img * P;
    const int wbase = bx * 2048 + w * 256;
    float vsum = 0.f;

    for (int it = 0; it < 4; ++it) {
        const int p0 = wbase + it * 64 + lane * 2;
        const int2 mid = *reinterpret_cast<const int2*>(mb + p0);
        float v[2][NCH];
#pragma unroll
        for (int e = 0; e < NCH; e++) {
            const float2 t = *reinterpret_cast<const float2*>(eb + (size_t)e * P + p0);
            v[0][e] = t.x; v[1][e] = t.y;
        }
        const int ids[2] = {mid.x, mid.y};
#pragma unroll
        for (int s = 0; s < 2; s++) {
            const int id = ids[s];
            const int row = ((id == 0) ? 1 : id) - 1;
            const float* mrow = &mut[row * STR];
            float sq = 0.f;
#pragma unroll
            for (int e = 0; e < NCH; e++) {
                const float d = v[s][e] - mrow[e];
                sq = fmaf(d, d, sq);
            }
            const float pd = (sq > 0.f) ? sqrtf(sq) : 0.f;
            const float tt = fmaxf(pd - DELTA_V, 0.f);
            vsum += (id != 0) ? (tt * tt * mrow[NCH]) : 0.f;
        }
    }

#pragma unroll
    for (int o = 16; o > 0; o >>= 1) vsum += __shfl_xor_sync(FULL, vsum, o);
    if (lane == 0) wred[w] = vsum;
    __syncthreads();
    if (tid == 0) {
        float s = 0.f;
#pragma unroll
        for (int i = 0; i < 8; i++) s += wred[i];
        atomicAdd(&g_vsum[img], s);
        __threadfence();                                   // publish before ticket
        const unsigned t = atomicInc(&g_tick, NVARBLK - 1); // wraps to 0 at 1024
        s_last = (t == NVARBLK - 1);
    }
    __syncthreads();
    if (!s_last) return;

    // ---- Fused finalize (one block; all other blocks fully done) ----
    __threadfence();
    __shared__ float smu[NIMG][32][NCH + 1];
    __shared__ float sv[NIMG], sd[NIMG], sr[NIMG], sva[NIMG];

    const float* ga = g_acc[w];                 // warp = image
    const float cnt = ga[lane * STR + NCH];     // lane <-> instance lane+1
    const bool pres = cnt > 0.f;
    const float cc = fmaxf(cnt, 1.f);
    float mu[NCH];
#pragma unroll
    for (int e = 0; e < NCH; e++) {
        mu[e] = ga[lane * STR + e] / cc;
        smu[w][lane][e] = mu[e];
    }
    const float var_s = g_vsum[w];
    __syncwarp();

    const unsigned pb = __ballot_sync(FULL, pres);
    const float n_inst = (float)__popc(pb);

    float sqm = 0.f;
#pragma unroll
    for (int e = 0; e < NCH; e++) sqm = fmaf(mu[e], mu[e], sqm);
    const float reg_l = pres ? ((sqm > 0.f) ? sqrtf(sqm) : 0.f) : 0.f;

    float dsum = 0.f, pcount = 0.f;
#pragma unroll 4
    for (int b = 1; b < 32; b++) {
        float dsq = 0.f;
#pragma unroll
        for (int e = 0; e < NCH; e++) {
            const float d = mu[e] - smu[w][b][e];
            dsq = fmaf(d, d, dsq);
        }
        if ((lane < b) && pres && ((pb >> b) & 1u)) {
            const float dd = (dsq > 0.f) ? sqrtf(dsq) : 0.f;
            const float tt = fmaxf(2.f * DELTA_D - dd, 0.f);
            dsum = fmaf(tt, tt, dsum);
            pcount += 1.f;
        }
    }

    const float reg_t = wsum(reg_l);
    const float dst_t = wsum(dsum);
    const float pcs   = wsum(pcount);

    if (lane == 0) {
        const float valid = (n_inst > 0.f) ? 1.f : 0.f;
        const float denom = fmaxf(n_inst, 1.f);
        sv[w]  = (var_s / denom) * valid;
        sr[w]  = (reg_t / denom) * valid;
        sd[w]  = (dst_t / fmaxf(pcs, 1.f)) * ((n_inst > 1.f) ? 1.f : 0.f) * valid;
        sva[w] = valid;
    }
    __syncthreads();

    if (tid == 0) {
        float vs = 0.f, v = 0.f, d = 0.f, r = 0.f;
        for (int i = 0; i < NIMG; i++) { vs += sva[i]; v += sv[i]; d += sd[i]; r += sr[i]; }
        vs = fmaxf(vs, 1.f);
        v /= vs; d /= vs; r /= vs;
        out[0] = v + d + GAMMA_W * r;
        out[1] = v;
        out[2] = d;
        out[3] = r;
    }

    // Re-zero scratch for the next graph replay (ticket already self-wrapped).
    float* a = &g_acc[0][0];
    for (int i = tid; i < NIMG * ACCN; i += 256) a[i] = 0.f;
    if (tid < NIMG) g_vsum[tid] = 0.f;
}

extern "C" void kernel_launch(void* const* d_in, const int* in_sizes, int n_in,
                              void* d_out, int out_size) {
    const float* emb = (const float*)d_in[0];
    const int* mask = (const int*)d_in[1];
    float* out = (float*)d_out;

    k_accum<<<dim3(64, NIMG), 256>>>(emb, mask);
    k_var<<<dim3(128, NIMG), 256>>>(emb, mask, out);
}

// round 15
// speedup vs baseline: 1.4067x; 1.0795x over previous
#include <cuda_runtime.h>
#include <math.h>

#define P 262144          // 512*512
#define NCH 16
#define NIMG 8
#define NID 32            // ids 1..32 at row id-1; id 0 excluded (never contributes)
#define STR 17            // g_acc row stride (global layout unchanged)
#define ACCN (NID * STR)  // 544 floats per image in g_acc
#define RREP 3            // rank replicas (R10 frontier)
// f32x2-packed per-warp accumulator:
//   row = 18 floats (8 float2 data slots ch(2j,2j+1) + count@16 + pad)
//   row stride 9 f2 -> 16 consecutive rows on distinct 64b bankpairs
//   replica stride 289 f2 (== 1 mod 16) -> same-row replicas on distinct bankpairs
#define RS 18             // floats per row
#define REPF 578          // floats per replica (= 289 f2)
#define WARPF (RREP * REPF) // 1734 floats/warp; 8 warps -> 55,488 B
#define DELTA_V 0.5f
#define DELTA_D 1.5f
#define GAMMA_W 0.001f
#define FULL 0xffffffffu

#define ADDX2(acc, val) do {                                                    \
    unsigned long long _a = *reinterpret_cast<unsigned long long*>(&(acc));     \
    unsigned long long _b = *reinterpret_cast<const unsigned long long*>(&(val));\
    asm("add.rn.f32x2 %0, %1, %2;" : "=l"(_a) : "l"(_a), "l"(_b));              \
    *reinterpret_cast<unsigned long long*>(&(acc)) = _a;                        \
} while (0)

// Scratch (zero-initialized at load; k_final re-zeroes after use per replay).
__device__ float g_acc[NIMG][ACCN];   // [(id-1)*17 + e], slot 16 = count
__device__ float g_vsum[NIMG];        // per-image sum of t * invc

// Pass 1: per-segment sums + counts. grid (128, 8) x 256 thr (R10 config).
// Scatter rounds use packed f32x2: 8x(LDS.64+ADD.f32x2+STS.64) per round
// instead of 17x(LDS.32+FADD+STS.32) -> ~2x fewer L1 wavefronts (the binder).
__global__ __launch_bounds__(256, 4) void k_accum(const float* __restrict__ emb,
                                                  const int* __restrict__ mask) {
    __shared__ __align__(16) float wacc[8][WARPF];   // 55.5 KB
    const int tid = threadIdx.x, w = tid >> 5, lane = tid & 31;
    const int img = blockIdx.y;

    for (int i = tid; i < 8 * WARPF; i += 256) (&wacc[0][0])[i] = 0.f;
    __syncthreads();

    const float* eb = emb + (size_t)img * NCH * P;
    const int*   mb = mask + (size_t)img * P;
    const int wbase = blockIdx.x * 2048 + w * 256;
    const unsigned below = (1u << lane) - 1u;

    for (int it = 0; it < 4; ++it) {
        const int p0 = wbase + it * 64 + lane * 2;
        const int2 mid = *reinterpret_cast<const int2*>(mb + p0);
        // vv[s][j] = channels (2j, 2j+1) of pixel s, packed for f32x2 adds
        float2 vv[2][8];
#pragma unroll
        for (int e = 0; e < NCH; e += 2) {
            const float2 ta = *reinterpret_cast<const float2*>(eb + (size_t)e * P + p0);
            const float2 tb = *reinterpret_cast<const float2*>(eb + (size_t)(e + 1) * P + p0);
            vv[0][e >> 1] = make_float2(ta.x, tb.x);
            vv[1][e >> 1] = make_float2(ta.y, tb.y);
        }
        const int ids[2] = {mid.x, mid.y};
#pragma unroll
        for (int s = 0; s < 2; s++) {
            const int id = ids[s];
            const bool go = (id != 0);
            const int key = go ? id : (64 + lane);        // unique keys park id0 lanes
            const unsigned peers = __match_any_sync(FULL, key);
            const int rank = __popc(peers & below);
            const int band = rank / RREP;
            const int rep  = rank - band * RREP;
            const float cntf = (float)__popc(peers);      // leader adds group count
            float* af = &wacc[w][rep * REPF + (id - 1) * RS];
            float2* a2 = reinterpret_cast<float2*>(af);
            for (int r = 0;; r++) {
                if (!__ballot_sync(FULL, go && band >= r)) break;
                if (go && band == r) {
#pragma unroll
                    for (int j = 0; j < 8; j++) {
                        float2 c = a2[j];                 // LDS.64
                        ADDX2(c, vv[s][j]);               // 1 packed add
                        a2[j] = c;                        // STS.64
                    }
                    if (rank == 0) af[16] += cntf;        // once per id-group
                }
            }
        }
    }
    __syncthreads();

    // Reduce 24 copies -> g_acc (global layout unchanged: stride 17, count@16)
    for (int i = tid; i < ACCN; i += 256) {
        const int row = i / STR, e = i % STR;             // e==16 -> count slot
        const int off = row * RS + e;
        float s = 0.f;
#pragma unroll
        for (int w2 = 0; w2 < 8; w2++) {
#pragma unroll
            for (int rp = 0; rp < RREP; rp++) s += wacc[w2][rp * REPF + off];
        }
        atomicAdd(&g_acc[img][i], s);
    }
}

// Pass 2: variance hinge as a pure reduction (EXACT R10 code).
__global__ __launch_bounds__(256, 5) void k_var(const float* __restrict__ emb,
                                                const int* __restrict__ mask) {
    __shared__ float mut[ACCN];          // row (id-1)*17: mean[0..15], slot16 = invc
    __shared__ float wred[8];
    const int tid = threadIdx.x, w = tid >> 5, lane = tid & 31;
    const int img = (NIMG - 1) - blockIdx.y;
    const int bx  = 127 - blockIdx.x;

    for (int i = tid; i < ACCN; i += 256) {
        const int row = i / STR, e = i % STR;
        const float cc = fmaxf(g_acc[img][row * STR + NCH], 1.f);
        mut[i] = (e == NCH) ? (1.f / cc) : (g_acc[img][row * STR + e] / cc);
    }
    __syncthreads();

    const float* eb = emb + (size_t)img * NCH * P;
    const int*   mb = mask + (size_t)img * P;
    const int wbase = bx * 2048 + w * 256;
    float vsum = 0.f;

    for (int it = 0; it < 4; ++it) {
        const int p0 = wbase + it * 64 + lane * 2;
        const int2 mid = *reinterpret_cast<const int2*>(mb + p0);
        float v[2][NCH];
#pragma unroll
        for (int e = 0; e < NCH; e++) {
            const float2 t = *reinterpret_cast<const float2*>(eb + (size_t)e * P + p0);
            v[0][e] = t.x; v[1][e] = t.y;
        }
        const int ids[2] = {mid.x, mid.y};
#pragma unroll
        for (int s = 0; s < 2; s++) {
            const int id = ids[s];
            const int row = ((id == 0) ? 1 : id) - 1;
            const float* mrow = &mut[row * STR];
            float sq = 0.f;
#pragma unroll
            for (int e = 0; e < NCH; e++) {
                const float d = v[s][e] - mrow[e];
                sq = fmaf(d, d, sq);
            }
            const float pd = (sq > 0.f) ? sqrtf(sq) : 0.f;
            const float tt = fmaxf(pd - DELTA_V, 0.f);
            vsum += (id != 0) ? (tt * tt * mrow[NCH]) : 0.f;
        }
    }

#pragma unroll
    for (int o = 16; o > 0; o >>= 1) vsum += __shfl_xor_sync(FULL, vsum, o);
    if (lane == 0) wred[w] = vsum;
    __syncthreads();
    if (w == 0) {
        float s = (lane < 8) ? wred[lane] : 0.f;
#pragma unroll
        for (int o = 4; o > 0; o >>= 1) s += __shfl_xor_sync(FULL, s, o);
        if (lane == 0) atomicAdd(&g_vsum[img], s);
    }
}

__device__ __forceinline__ float wsum(float x) {
#pragma unroll
    for (int o = 16; o > 0; o >>= 1) x += __shfl_xor_sync(FULL, x, o);
    return x;
}

// Finalize: one block, warp = image (EXACT R10 code).
__global__ __launch_bounds__(256) void k_final(float* __restrict__ out) {
    __shared__ float smu[NIMG][32][NCH + 1];
    __shared__ float sv[NIMG], sd[NIMG], sr[NIMG], sva[NIMG];
    const int tid = threadIdx.x, w = tid >> 5, lane = tid & 31;

    const float* ga = g_acc[w];
    const float cnt = ga[lane * STR + NCH];     // lane <-> instance lane+1
    const bool pres = cnt > 0.f;
    const float cc = fmaxf(cnt, 1.f);
    float mu[NCH];
#pragma unroll
    for (int e = 0; e < NCH; e++) {
        mu[e] = ga[lane * STR + e] / cc;
        smu[w][lane][e] = mu[e];
    }
    const float var_s = g_vsum[w];
    __syncwarp();

    const unsigned pb = __ballot_sync(FULL, pres);
    const float n_inst = (float)__popc(pb);

    float sqm = 0.f;
#pragma unroll
    for (int e = 0; e < NCH; e++) sqm = fmaf(mu[e], mu[e], sqm);
    const float reg_l = pres ? ((sqm > 0.f) ? sqrtf(sqm) : 0.f) : 0.f;

    float dsum = 0.f, pcount = 0.f;
#pragma unroll 4
    for (int b = 1; b < 32; b++) {
        float dsq = 0.f;
#pragma unroll
        for (int e = 0; e < NCH; e++) {
            const float d = mu[e] - smu[w][b][e];
            dsq = fmaf(d, d, dsq);
        }
        if ((lane < b) && pres && ((pb >> b) & 1u)) {
            const float dd = (dsq > 0.f) ? sqrtf(dsq) : 0.f;
            const float tt = fmaxf(2.f * DELTA_D - dd, 0.f);
            dsum = fmaf(tt, tt, dsum);
            pcount += 1.f;
        }
    }

    const float reg_t = wsum(reg_l);
    const float dst_t = wsum(dsum);
    const float pcs   = wsum(pcount);

    if (lane == 0) {
        const float valid = (n_inst > 0.f) ? 1.f : 0.f;
        const float denom = fmaxf(n_inst, 1.f);
        sv[w]  = (var_s / denom) * valid;
        sr[w]  = (reg_t / denom) * valid;
        sd[w]  = (dst_t / fmaxf(pcs, 1.f)) * ((n_inst > 1.f) ? 1.f : 0.f) * valid;
        sva[w] = valid;
    }
    __syncthreads();

    if (tid == 0) {
        float vs = 0.f, v = 0.f, d = 0.f, r = 0.f;
        for (int i = 0; i < NIMG; i++) { vs += sva[i]; v += sv[i]; d += sd[i]; r += sr[i]; }
        vs = fmaxf(vs, 1.f);
        v /= vs; d /= vs; r /= vs;
        out[0] = v + d + GAMMA_W * r;
        out[1] = v;
        out[2] = d;
        out[3] = r;
    }

    // Re-zero scratch for the next graph replay (all reads happened above).
    float* a = &g_acc[0][0];
    for (int i = tid; i < NIMG * ACCN; i += 256) a[i] = 0.f;
    if (tid < NIMG) g_vsum[tid] = 0.f;
}

extern "C" void kernel_launch(void* const* d_in, const int* in_sizes, int n_in,
                              void* d_out, int out_size) {
    const float* emb = (const float*)d_in[0];
    const int* mask = (const int*)d_in[1];
    float* out = (float*)d_out;

    k_accum<<<dim3(128, NIMG), 256>>>(emb, mask);
    k_var<<<dim3(128, NIMG), 256>>>(emb, mask);
    k_final<<<1, 256>>>(out);
}